// round 5
// baseline (speedup 1.0000x reference)
#include <cuda_runtime.h>
#include <cuda_fp16.h>
#include <math.h>

#define NPL   80
#define NYI   384
#define OSN   768
#define PAD   192
#define PLSZ  (768*768)
#define HALF_OUT ((size_t)NPL*NYI*NYI)

__device__ __half2 g_bufA[(size_t)NPL*OSN*OSN];
__device__ __half2 g_bufB[(size_t)NPL*OSN*OSN];
__device__ float2  g_twid[OSN];   // e^{-2*pi*i*j/768}

// smem swizzle on float2-element index: fold bits 7-9 into bits 2-4
#define SWZ(e) ((e) ^ ((((e) >> 7) & 7) << 2))

// W16^j, j = 0..9
__constant__ float2 c_w16[10] = {
    { 1.0f,            0.0f},
    { 0.9238795325f,  -0.3826834324f},
    { 0.7071067812f,  -0.7071067812f},
    { 0.3826834324f,  -0.9238795325f},
    { 0.0f,           -1.0f},
    {-0.3826834324f,  -0.9238795325f},
    {-0.7071067812f,  -0.7071067812f},
    {-0.9238795325f,  -0.3826834324f},
    {-1.0f,            0.0f},
    {-0.9238795325f,   0.3826834324f}
};

__device__ __forceinline__ float2 cmulf(float2 a, float2 b){
    return make_float2(a.x*b.x - a.y*b.y, a.x*b.y + a.y*b.x);
}
__device__ __forceinline__ float2 caddf(float2 a, float2 b){ return make_float2(a.x+b.x, a.y+b.y); }
__device__ __forceinline__ float2 csubf(float2 a, float2 b){ return make_float2(a.x-b.x, a.y-b.y); }

template<bool INV>
__device__ __forceinline__ float2 twmul(float2 a, float2 w){
    if (INV) w.y = -w.y;
    return cmulf(a, w);
}

__device__ __forceinline__ unsigned f2h(float2 v){
    __half2 h = __floats2half2_rn(v.x, v.y);
    return *reinterpret_cast<unsigned*>(&h);
}
__device__ __forceinline__ float2 h2f(unsigned u){
    __half2 h = *reinterpret_cast<__half2*>(&u);
    return __half22float2(h);
}

__global__ void k_twid(){
    int j = blockIdx.x*blockDim.x + threadIdx.x;
    if (j < OSN){
        double a = -2.0*3.14159265358979323846*(double)j/768.0;
        g_twid[j] = make_float2((float)cos(a), (float)sin(a));
    }
}

template<bool INV>
__device__ __forceinline__ void dft4(float2 &a0, float2 &a1, float2 &a2, float2 &a3){
    float2 t0=caddf(a0,a2), t1=csubf(a0,a2), t2=caddf(a1,a3), t3=csubf(a1,a3);
    a0 = caddf(t0,t2);  a2 = csubf(t0,t2);
    if (!INV){ a1 = make_float2(t1.x + t3.y, t1.y - t3.x);
               a3 = make_float2(t1.x - t3.y, t1.y + t3.x); }
    else     { a1 = make_float2(t1.x - t3.y, t1.y + t3.x);
               a3 = make_float2(t1.x + t3.y, t1.y - t3.x); }
}

// dft16 pass 1 (in place over a[16], decomposition n = n2 + 4*j)
template<bool INV>
__device__ __forceinline__ void dft16_pass1(float2 a[16]){
    #pragma unroll
    for (int n2 = 0; n2 < 4; ++n2)
        dft4<INV>(a[n2], a[n2+4], a[n2+8], a[n2+12]);
}
// dft16 pass 2, group k1: consumes a[4k1..4k1+3], yields X[k1+4k2] in y[k2]
template<bool INV>
__device__ __forceinline__ void dft16_pass2(const float2 a[16], int k1, float2 y[4]){
    y[0] = a[4*k1];
    y[1] = twmul<INV>(a[4*k1+1], c_w16[k1]);
    y[2] = twmul<INV>(a[4*k1+2], c_w16[2*k1]);
    y[3] = twmul<INV>(a[4*k1+3], c_w16[3*k1]);
    dft4<INV>(y[0], y[1], y[2], y[3]);
}

// 768-pt Stockham FFT, radices [16,16,3], NB interleaved batches, 48*NB threads.
// s0 -> (A) -> s1 -> (B) -> s0 -> (C) -> s1. Result in s1.
template<int NB, bool INV>
__device__ __forceinline__ float2* fft768(float2* s0, float2* s1, int tid){
    const int col = tid % NB;
    const int idx = tid / NB;           // 0..47
    float2 a[16];
    // ---- Stage A: l=1, twiddle-free ----
    #pragma unroll
    for (int r = 0; r < 16; ++r) a[r] = s0[SWZ((idx + 48*r)*NB + col)];
    dft16_pass1<INV>(a);
    #pragma unroll
    for (int k1 = 0; k1 < 4; ++k1){
        float2 y[4];
        dft16_pass2<INV>(a, k1, y);
        #pragma unroll
        for (int k2 = 0; k2 < 4; ++k2)
            s1[SWZ((idx*16 + k1 + 4*k2)*NB + col)] = y[k2];
    }
    __syncthreads();
    // ---- Stage B: l=16, twiddle W768^{3*r*k} ----
    {
        const int k = idx & 15, j = idx >> 4;
        #pragma unroll
        for (int r = 0; r < 16; ++r) a[r] = s1[SWZ((idx + 48*r)*NB + col)];
        #pragma unroll
        for (int r = 1; r < 16; ++r) a[r] = twmul<INV>(a[r], g_twid[3*r*k]);
        dft16_pass1<INV>(a);
        #pragma unroll
        for (int k1 = 0; k1 < 4; ++k1){
            float2 y[4];
            dft16_pass2<INV>(a, k1, y);
            #pragma unroll
            for (int k2 = 0; k2 < 4; ++k2)
                s0[SWZ((j*256 + k + 16*(k1 + 4*k2))*NB + col)] = y[k2];
        }
    }
    __syncthreads();
    // ---- Stage C: l=256, radix-3 ----
    #pragma unroll 1
    for (int w = tid; w < 256*NB; w += 48*NB){
        int c3 = w % NB, k = w / NB;
        float2 a0 = s0[SWZ((k      )*NB + c3)];
        float2 a1 = s0[SWZ((k + 256)*NB + c3)];
        float2 a2 = s0[SWZ((k + 512)*NB + c3)];
        a1 = twmul<INV>(a1, g_twid[k]);
        a2 = twmul<INV>(a2, g_twid[2*k]);
        float2 t = caddf(a1, a2);
        float2 d = csubf(a1, a2);
        float2 b0 = caddf(a0, t);
        float2 u  = make_float2(a0.x - 0.5f*t.x, a0.y - 0.5f*t.y);
        const float S = INV ? 0.86602540378443864676f : -0.86602540378443864676f;
        float2 b1 = make_float2(u.x - S*d.y, u.y + S*d.x);
        float2 b2 = make_float2(u.x + S*d.y, u.y - S*d.x);
        s1[SWZ((k      )*NB + c3)] = b0;
        s1[SWZ((k + 256)*NB + c3)] = b1;
        s1[SWZ((k + 512)*NB + c3)] = b2;
    }
    __syncthreads();
    return s1;
}

// K1: pad + checkerboard + forward row FFT. 4 rows/block, 192 thr.
__global__ void __launch_bounds__(192) k_row_fwd(const float* __restrict__ re,
                                                 const float* __restrict__ im){
    extern __shared__ float2 sm[];
    float2* s0 = sm; float2* s1 = sm + 3072;
    int p = blockIdx.y, iy0 = blockIdx.x*4, tid = threadIdx.x;
    #pragma unroll 1
    for (int w = tid; w < 3072; w += 192){
        int x = w >> 2, r = w & 3;
        float2 v = make_float2(0.f, 0.f);
        if (x >= PAD && x < PAD + NYI){
            int ix = x - PAD, iy = iy0 + r;
            size_t o = ((size_t)p*NYI + iy)*NYI + ix;
            float s = ((iy + ix) & 1) ? -1.f : 1.f;
            v.x = s*re[o]; v.y = s*im[o];
        }
        s0[SWZ(w)] = v;                  // e = x*4 + r = w
    }
    __syncthreads();
    float2* o = fft768<4,false>(s0, s1, tid);
    #pragma unroll 1
    for (int w = tid; w < 3072; w += 192){
        int x = w >> 2, r = w & 3;
        *reinterpret_cast<unsigned*>(
            &g_bufA[((size_t)p*OSN + PAD + iy0 + r)*OSN + x]) = f2h(o[SWZ(w)]);
    }
}

// K2: forward column FFT. 8 cols/block, 384 thr, pruned central-384 load.
__global__ void __launch_bounds__(384) k_col_fwd(){
    extern __shared__ float2 sm[];
    float2* s0 = sm; float2* s1 = sm + 6144;
    int p = blockIdx.y, x0 = blockIdx.x*8, tid = threadIdx.x;
    #pragma unroll 1
    for (int w = tid; w < 6144; w += 384){
        int y = w >> 3, col = w & 7;
        float2 v = make_float2(0.f, 0.f);
        if (y >= PAD && y < PAD + NYI)
            v = h2f(*reinterpret_cast<const unsigned*>(
                &g_bufA[((size_t)p*OSN + y)*OSN + x0 + col]));
        s0[SWZ(w)] = v;                  // e = y*8 + col = w
    }
    __syncthreads();
    float2* o = fft768<8,false>(s0, s1, tid);
    #pragma unroll 1
    for (int w = tid; w < 6144; w += 384){
        int y = w >> 3, col = w & 7;
        *reinterpret_cast<unsigned*>(
            &g_bufB[((size_t)p*OSN + y)*OSN + x0 + col]) = f2h(o[SWZ(w)]);
    }
}

// K3: pointwise 5x5 complex subspace mixing across 16 coils, 2-coil unroll.
__global__ void __launch_bounds__(256) k_einsum(const float* __restrict__ kre,
                                                const float* __restrict__ kim){
    int px = blockIdx.x*256 + threadIdx.x;
    if (px >= PLSZ) return;
    const float sc = 1.0f/589824.0f;
    float2 kv[25];
    #pragma unroll
    for (int q = 0; q < 25; ++q)
        kv[q] = make_float2(sc*kre[(size_t)q*PLSZ + px], sc*kim[(size_t)q*PLSZ + px]);
    #pragma unroll 1
    for (int c = 0; c < 16; c += 2){
        float2 v0[5], v1[5];
        #pragma unroll
        for (int a = 0; a < 5; ++a){
            v0[a] = __half22float2(g_bufB[((size_t)(a*16 + c    ))*PLSZ + px]);
            v1[a] = __half22float2(g_bufB[((size_t)(a*16 + c + 1))*PLSZ + px]);
        }
        #pragma unroll
        for (int b = 0; b < 5; ++b){
            float2 a0 = make_float2(0.f,0.f), a1 = make_float2(0.f,0.f);
            #pragma unroll
            for (int a = 0; a < 5; ++a){
                float2 k2 = kv[b*5 + a];
                a0.x += k2.x*v0[a].x - k2.y*v0[a].y;
                a0.y += k2.x*v0[a].y + k2.y*v0[a].x;
                a1.x += k2.x*v1[a].x - k2.y*v1[a].y;
                a1.y += k2.x*v1[a].y + k2.y*v1[a].x;
            }
            g_bufA[((size_t)(b*16 + c    ))*PLSZ + px] = __floats2half2_rn(a0.x, a0.y);
            g_bufA[((size_t)(b*16 + c + 1))*PLSZ + px] = __floats2half2_rn(a1.x, a1.y);
        }
    }
}

// K4: inverse column FFT. 8 cols/block, 384 thr, writes only central 384 rows.
__global__ void __launch_bounds__(384) k_col_inv(){
    extern __shared__ float2 sm[];
    float2* s0 = sm; float2* s1 = sm + 6144;
    int p = blockIdx.y, x0 = blockIdx.x*8, tid = threadIdx.x;
    #pragma unroll 1
    for (int w = tid; w < 6144; w += 384){
        int y = w >> 3, col = w & 7;
        s0[SWZ(w)] = h2f(*reinterpret_cast<const unsigned*>(
            &g_bufA[((size_t)p*OSN + y)*OSN + x0 + col]));
    }
    __syncthreads();
    float2* o = fft768<8,true>(s0, s1, tid);
    #pragma unroll 1
    for (int w = tid; w < 3072; w += 384){
        int yy = w >> 3, col = w & 7;
        int y = PAD + yy;
        *reinterpret_cast<unsigned*>(
            &g_bufB[((size_t)p*OSN + y)*OSN + x0 + col]) = f2h(o[SWZ(y*8 + col)]);
    }
}

// K5: inverse row FFT. 4 rows/block, 192 thr, crop + checkerboard, fp32 out.
__global__ void __launch_bounds__(192) k_row_inv(float* __restrict__ out){
    extern __shared__ float2 sm[];
    float2* s0 = sm; float2* s1 = sm + 3072;
    int p = blockIdx.y, oy0 = blockIdx.x*4, tid = threadIdx.x;
    #pragma unroll 1
    for (int w = tid; w < 3072; w += 192){
        int x = w >> 2, r = w & 3;
        s0[SWZ(w)] = h2f(*reinterpret_cast<const unsigned*>(
            &g_bufB[((size_t)p*OSN + PAD + oy0 + r)*OSN + x]));
    }
    __syncthreads();
    float2* o = fft768<4,true>(s0, s1, tid);
    #pragma unroll 1
    for (int w = tid; w < 1536; w += 192){
        int ox = w >> 2, r = w & 3;
        int oy = oy0 + r;
        float2 v = o[SWZ((PAD + ox)*4 + r)];
        float s = ((oy + ox) & 1) ? -1.f : 1.f;
        size_t off = ((size_t)p*NYI + oy)*NYI + ox;
        out[off]            = s*v.x;
        out[off + HALF_OUT] = s*v.y;
    }
}

extern "C" void kernel_launch(void* const* d_in, const int* in_sizes, int n_in,
                              void* d_out, int out_size){
    const float* ire = (const float*)d_in[0];
    const float* iim = (const float*)d_in[1];
    const float* kre = (const float*)d_in[2];
    const float* kim = (const float*)d_in[3];
    float* out = (float*)d_out;

    const int SM_ROW = 2*3072*sizeof(float2);   // 49152
    const int SM_COL = 2*6144*sizeof(float2);   // 98304
    cudaFuncSetAttribute(k_row_fwd, cudaFuncAttributeMaxDynamicSharedMemorySize, SM_ROW);
    cudaFuncSetAttribute(k_row_inv, cudaFuncAttributeMaxDynamicSharedMemorySize, SM_ROW);
    cudaFuncSetAttribute(k_col_fwd, cudaFuncAttributeMaxDynamicSharedMemorySize, SM_COL);
    cudaFuncSetAttribute(k_col_inv, cudaFuncAttributeMaxDynamicSharedMemorySize, SM_COL);

    k_twid<<<3, 256>>>();

    k_row_fwd<<<dim3(96, NPL), 192, SM_ROW>>>(ire, iim);
    k_col_fwd<<<dim3(96, NPL), 384, SM_COL>>>();
    k_einsum<<<(PLSZ + 255)/256, 256>>>(kre, kim);
    k_col_inv<<<dim3(96, NPL), 384, SM_COL>>>();
    k_row_inv<<<dim3(96, NPL), 192, SM_ROW>>>(out);
}